// round 7
// baseline (speedup 1.0000x reference)
#include <cuda_runtime.h>
#include <math.h>

#define Bn 4
#define Tn 8192
#define Dn 512
#define Sn 16
#define PARTS 64   // 256 blocks / 4 batches in the fused attn+G pass

// Scratch (static device globals — allocation-free per harness rules)
__device__ float g_attn [Bn*Tn*Sn];          // 2 MB
__device__ float g_Gpart[Bn*PARTS*Sn*Dn];    // 8 MB
__device__ float g_G    [Bn*Sn*Dn];
__device__ float g_H    [Bn*Sn*Dn];
__device__ float g_M    [Bn*Sn*Dn];

__device__ __forceinline__ unsigned f2tf32(float f) {
    unsigned r; asm("cvt.rna.tf32.f32 %0, %1;" : "=r"(r) : "f"(f));
    return r;
}

__device__ __forceinline__ void mma_tf32(float c[4],
    unsigned a0, unsigned a1, unsigned a2, unsigned a3,
    unsigned b0, unsigned b1) {
    asm("mma.sync.aligned.m16n8k8.row.col.f32.tf32.tf32.f32 "
        "{%0,%1,%2,%3}, {%4,%5,%6,%7}, {%8,%9}, {%0,%1,%2,%3};"
        : "+f"(c[0]), "+f"(c[1]), "+f"(c[2]), "+f"(c[3])
        : "r"(a0), "r"(a1), "r"(a2), "r"(a3), "r"(b0), "r"(b1));
}

// 8-lane reduction (lanes differing in bits 0..2)
__device__ __forceinline__ float red8(float v) {
    v += __shfl_xor_sync(0xffffffffu, v, 1);
    v += __shfl_xor_sync(0xffffffffu, v, 2);
    v += __shfl_xor_sync(0xffffffffu, v, 4);
    return v;
}

// ---------------------------------------------------------------------------
// Kernel 1 (fused): attention weights (tf32 MMA for xc, fp32 x2/softmax)
// + partial G = attn^T x via tf32 MMA. Grid 256 x 256 thr, 128 tokens/block.
// ---------------------------------------------------------------------------
__global__ __launch_bounds__(256) void k_attn_g(const float* __restrict__ x,
                                                const float* __restrict__ centers,
                                                const float* __restrict__ log_scales) {
    __shared__ float    s_x   [128 * 36];    // tf32 x chunk, padded (18 KB)
    __shared__ unsigned s_bf  [512];         // B fragments (centers) per chunk (2 KB)
    __shared__ float    s_xc  [128 * 17];    // XC, padded (8.7 KB)
    __shared__ float    s_attn[128 * Sn];    // 8 KB
    __shared__ unsigned s_bfa [2048];        // B fragments (attn) for G mma (8 KB)
    __shared__ float    s_x2  [128];
    __shared__ float    s_part[256];
    __shared__ float    s_inv [Sn], s_bias[Sn];

    int tid  = threadIdx.x;
    int warp = tid >> 5, lane = tid & 31;
    int gid  = lane >> 2, tg = lane & 3;     // mma fragment coords
    int grp  = lane >> 3, li = lane & 7;     // x2 groups
    long long tok0 = (long long)blockIdx.x * 128;
    const float* xb = x + tok0 * Dn;

    // ---- scale/bias precompute: c2 via 16 threads per splat ----
    {
        int sp = tid >> 4, p16 = tid & 15;
        const float4* cr = (const float4*)(centers + (long long)sp * Dn);
        float c2 = 0.f;
#pragma unroll
        for (int j = 0; j < 8; j++) {
            float4 v = cr[p16 + j * 16];
            c2 += v.x * v.x + v.y * v.y + v.z * v.z + v.w * v.w;
        }
        s_part[tid] = c2;
        __syncthreads();
        if (tid < Sn) {
            float c2t = 0.f;
#pragma unroll
            for (int k = 0; k < 16; k++) c2t += s_part[tid * 16 + k];
            float s = expf(log_scales[tid]);
            s = fminf(fmaxf(s, 0.1f), 2.0f);
            float inv = -0.5f / (s * s);
            s_inv[tid]  = inv;
            s_bias[tid] = inv * c2t;
        }
    }

    // ---- Phase 1: XC = x . centers^T via tf32 mma, x2 in fp32 ----
    float xcacc[2][4];
#pragma unroll
    for (int h = 0; h < 2; h++)
#pragma unroll
        for (int r = 0; r < 4; r++) xcacc[h][r] = 0.f;
    float x2r[4] = {0.f, 0.f, 0.f, 0.f};
    int tlw = warp * 16;                     // warp's m-tile token base
    int tlg = tlw + grp * 4;                 // x2 group token base

#pragma unroll 1
    for (int c = 0; c < 16; c++) {
        // stage x chunk (cols c*32..+31) as tf32, padded stride 36
#pragma unroll
        for (int i = 0; i < 4; i++) {
            int idx = tid + i * 256;         // 0..1023 = 128 rows x 8 float4
            int row = idx >> 3, c4 = idx & 7;
            float4 v = ((const float4*)(xb + (long long)row * Dn))[c * 8 + c4];
            float4 t;
            t.x = __uint_as_float(f2tf32(v.x));
            t.y = __uint_as_float(f2tf32(v.y));
            t.z = __uint_as_float(f2tf32(v.z));
            t.w = __uint_as_float(f2tf32(v.w));
            *(float4*)&s_x[row * 36 + c4 * 4] = t;
        }
        // B fragments for this chunk: [kit8][h][which][lane]
#pragma unroll
        for (int i = 0; i < 2; i++) {
            int e = tid + i * 256;           // 0..511
            int kit8 = e >> 7, rem = e & 127;
            int h = rem >> 6, which = (rem >> 5) & 1, L = rem & 31;
            int k  = c * 32 + kit8 * 8 + (L & 3) + which * 4;
            int sp = h * 8 + (L >> 2);
            s_bf[e] = f2tf32(centers[(long long)sp * Dn + k]);
        }
        // x2 partials from gmem (lines are L1-hot from staging)
#pragma unroll
        for (int i = 0; i < 4; i++) {
            float4 v = ((const float4*)(xb + (long long)(tlg + i) * Dn))[c * 8 + li];
            x2r[i] += v.x * v.x + v.y * v.y + v.z * v.z + v.w * v.w;
        }
        __syncthreads();
        // 4 k-iterations of m16n8k8 per n-half
#pragma unroll
        for (int kit8 = 0; kit8 < 4; kit8++) {
            int kb = kit8 * 8;
            unsigned a0 = __float_as_uint(s_x[(tlw + gid)     * 36 + kb + tg]);
            unsigned a1 = __float_as_uint(s_x[(tlw + gid + 8) * 36 + kb + tg]);
            unsigned a2 = __float_as_uint(s_x[(tlw + gid)     * 36 + kb + tg + 4]);
            unsigned a3 = __float_as_uint(s_x[(tlw + gid + 8) * 36 + kb + tg + 4]);
#pragma unroll
            for (int h = 0; h < 2; h++) {
                unsigned b0 = s_bf[kit8 * 128 + h * 64 + lane];
                unsigned b1 = s_bf[kit8 * 128 + h * 64 + 32 + lane];
                mma_tf32(xcacc[h], a0, a1, a2, a3, b0, b1);
            }
        }
        __syncthreads();
    }

    // write XC fragments to padded smem
#pragma unroll
    for (int h = 0; h < 2; h++) {
        int col = h * 8 + tg * 2;
        s_xc[(tlw + gid)     * 17 + col]     = xcacc[h][0];
        s_xc[(tlw + gid)     * 17 + col + 1] = xcacc[h][1];
        s_xc[(tlw + gid + 8) * 17 + col]     = xcacc[h][2];
        s_xc[(tlw + gid + 8) * 17 + col + 1] = xcacc[h][3];
    }
#pragma unroll
    for (int i = 0; i < 4; i++) x2r[i] = red8(x2r[i]);
    if (li < 4) s_x2[tlg + li] = x2r[li];
    __syncthreads();

    // per-token softmax (threads 0..127)
    if (tid < 128) {
        float x2 = s_x2[tid];
        float l[Sn];
        float m = -1e30f;
#pragma unroll
        for (int s = 0; s < Sn; s++) {
            l[s] = s_inv[s] * (x2 - 2.f * s_xc[tid * 17 + s]) + s_bias[s];
            m = fmaxf(m, l[s]);
        }
        float sum = 0.f;
#pragma unroll
        for (int s = 0; s < Sn; s++) { l[s] = __expf(l[s] - m); sum += l[s]; }
        float r = 1.f / sum;
#pragma unroll
        for (int s = 0; s < Sn; s++) s_attn[tid * Sn + s] = l[s] * r;
    }
    __syncthreads();

    // coalesced copy s_attn -> g_attn, and build attn B-fragment table for G mma
    for (int i = tid; i < 128 * Sn / 4; i += 256)
        ((float4*)(g_attn + tok0 * Sn))[i] = ((const float4*)s_attn)[i];
#pragma unroll
    for (int i = 0; i < 8; i++) {
        int e = tid + i * 256;               // 0..2047
        int ks = e >> 7, rem = e & 127;
        int h = rem >> 6, reg = (rem >> 5) & 1, L = rem & 31;
        int t = ks * 8 + (L & 3) + reg * 4;
        int s = h * 8 + (L >> 2);
        s_bfa[e] = f2tf32(s_attn[t * Sn + s]);
    }
    __syncthreads();

    // -------- Phase 2: G^T[d,s] = sum_t x[t,d] attn[t,s] via tf32 MMA --------
    // warp owns dims [warp*64, warp*64+64): 4 m-tiles of 16 dims; k = 128 tokens.
    int b = (int)(tok0 / Tn);
    int p = (int)((tok0 % Tn) / 128);
    float* gp = g_Gpart + ((long long)(b * PARTS + p) * Sn * Dn);

#pragma unroll
    for (int mt = 0; mt < 4; mt++) {
        int d0 = warp * 64 + mt * 16;
        float c[2][4];
#pragma unroll
        for (int h = 0; h < 2; h++)
#pragma unroll
            for (int r = 0; r < 4; r++) c[h][r] = 0.f;

#pragma unroll 4
        for (int ks = 0; ks < 16; ks++) {
            int t0 = ks * 8;
            const float* r0 = xb + (t0 + tg)     * Dn + d0 + gid;
            const float* r1 = xb + (t0 + tg + 4) * Dn + d0 + gid;
            unsigned a0 = f2tf32(r0[0]);
            unsigned a1 = f2tf32(r0[8]);
            unsigned a2 = f2tf32(r1[0]);
            unsigned a3 = f2tf32(r1[8]);
#pragma unroll
            for (int h = 0; h < 2; h++) {
                unsigned b0 = s_bfa[ks * 128 + h * 64 + lane];
                unsigned b1 = s_bfa[ks * 128 + h * 64 + 32 + lane];
                mma_tf32(c[h], a0, a1, a2, a3, b0, b1);
            }
        }
        // store: C[dim][splat] -> gp[splat*Dn + dim]
#pragma unroll
        for (int h = 0; h < 2; h++) {
            int s0 = h * 8 + 2 * tg;
            gp[(long long)s0       * Dn + d0 + gid]     = c[h][0];
            gp[(long long)(s0 + 1) * Dn + d0 + gid]     = c[h][1];
            gp[(long long)s0       * Dn + d0 + gid + 8] = c[h][2];
            gp[(long long)(s0 + 1) * Dn + d0 + gid + 8] = c[h][3];
        }
    }
}

// ---------------------------------------------------------------------------
// Kernel 2: reduce 64 partials -> G. 32768 outputs. Grid 128 x 256 thr.
// ---------------------------------------------------------------------------
__global__ void k_reduce() {
    int idx = blockIdx.x * blockDim.x + threadIdx.x;   // < Bn*Sn*Dn = 32768
    int b = idx >> 13;
    int r = idx & 8191;
    float sum = 0.f;
#pragma unroll
    for (int p = 0; p < PARTS; p++)
        sum += g_Gpart[(long long)(b * PARTS + p) * (Sn * Dn) + r];
    g_G[idx] = sum;
}

// ---------------------------------------------------------------------------
// Kernel 3: small GEMM out[row][k] = sum_d in[row][d] * W[k][d].
// Grid (64 col-chunks, 4 batches, 2 row-halves) x 256 thr: 512 blocks.
// Block stages 8 rows (16KB); warp per column; acc[8]; 9-shfl scatter reduce.
// ---------------------------------------------------------------------------
__global__ __launch_bounds__(256) void k_small_gemm(const float* __restrict__ W, int stage) {
    const float* in  = (stage == 0) ? g_G : g_H;
    float*       out = (stage == 0) ? g_H : g_M;
    __shared__ float4 s_in[8 * 128];         // 16 KB

    int tid = threadIdx.x, warp = tid >> 5, lane = tid & 31;
    int kc = blockIdx.x;                     // 0..63 column chunk
    int b  = blockIdx.y;                     // 0..3 batch
    int rh = blockIdx.z;                     // 0..1 row half

    const float4* src = (const float4*)(in + ((long long)b * 16 + rh * 8) * Dn);
#pragma unroll
    for (int i = 0; i < 4; i++) s_in[tid + i * 256] = src[tid + i * 256];
    __syncthreads();

    int k = kc * 8 + warp;                   // output column, 0..511
    const float4* wr = (const float4*)(W + (long long)k * Dn);
    float4 w0 = wr[lane], w1 = wr[lane + 32], w2 = wr[lane + 64], w3 = wr[lane + 96];

    float acc[8];
#pragma unroll
    for (int r = 0; r < 8; r++) {
        float4 g0 = s_in[r * 128 + lane];
        float4 g1 = s_in[r * 128 + lane + 32];
        float4 g2 = s_in[r * 128 + lane + 64];
        float4 g3 = s_in[r * 128 + lane + 96];
        acc[r] = w0.x*g0.x + w0.y*g0.y + w0.z*g0.z + w0.w*g0.w
               + w1.x*g1.x + w1.y*g1.y + w1.z*g1.z + w1.w*g1.w
               + w2.x*g2.x + w2.y*g2.y + w2.z*g2.z + w2.w*g2.w
               + w3.x*g3.x + w3.y*g3.y + w3.z*g3.z + w3.w*g3.w;
    }
    // scatter-reduce 8 values over lane bits {4,3,2}, then close bits {0,1}
#pragma unroll
    for (int step = 16, n = 4; n >= 1; step >>= 1, n >>= 1) {
        bool hi = (lane & step) != 0;
#pragma unroll
        for (int i = 0; i < n; i++) {
            float send = hi ? acc[i] : acc[i + n];
            float recv = __shfl_xor_sync(0xffffffffu, send, step);
            acc[i] = (hi ? acc[i + n] : acc[i]) + recv;
        }
    }
    float v = acc[0];
    v += __shfl_xor_sync(0xffffffffu, v, 1);
    v += __shfl_xor_sync(0xffffffffu, v, 2);
    int row = (lane >> 2) & 7;
    if ((lane & 3) == 0)
        out[((long long)b * 16 + rh * 8 + row) * Dn + k] = v;
}

// ---------------------------------------------------------------------------
// Kernel 4: y[t,:] = sum_s attn[t,s] * M[b,s,:]. Grid 512 x 256 thr,
// 64 tokens/block; M columns in registers; float2 stores. (near DRAM floor)
// ---------------------------------------------------------------------------
__global__ __launch_bounds__(256) void k_out(float* __restrict__ y) {
    __shared__ float s_a[64 * Sn];           // 4 KB attn tile
    int tid = threadIdx.x;
    long long tok0 = (long long)blockIdx.x * 64;
    int b = (int)(tok0 / Tn);

    ((float4*)s_a)[tid] = ((const float4*)(g_attn + tok0 * Sn))[tid];  // 256 float4
    __syncthreads();

    const float* Mb = g_M + (long long)b * Sn * Dn;
    float2 m[Sn];
#pragma unroll
    for (int s = 0; s < Sn; s++) m[s] = ((const float2*)(Mb + s * Dn))[tid];

    float* yb = y + tok0 * Dn;
#pragma unroll 2
    for (int t = 0; t < 64; t++) {
        const float4* ar = (const float4*)&s_a[t * Sn];
        float2 o; o.x = 0.f; o.y = 0.f;
#pragma unroll
        for (int q = 0; q < 4; q++) {
            float4 a = ar[q];
            o.x += a.x * m[q*4+0].x + a.y * m[q*4+1].x + a.z * m[q*4+2].x + a.w * m[q*4+3].x;
            o.y += a.x * m[q*4+0].y + a.y * m[q*4+1].y + a.z * m[q*4+2].y + a.w * m[q*4+3].y;
        }
        ((float2*)(yb + (long long)t * Dn))[tid] = o;
    }
}

// ---------------------------------------------------------------------------
extern "C" void kernel_launch(void* const* d_in, const int* in_sizes, int n_in,
                              void* d_out, int out_size) {
    (void)in_sizes; (void)n_in; (void)out_size;
    const float* x          = (const float*)d_in[0];   // [B,T,D]
    const float* centers    = (const float*)d_in[1];   // [S,D]
    const float* log_scales = (const float*)d_in[2];   // [S]
    const float* Wv         = (const float*)d_in[3];   // [D,D]
    const float* Wo         = (const float*)d_in[4];   // [D,D]
    float* y = (float*)d_out;                          // [B,T,D] fp32

    k_attn_g<<<256, 256>>>(x, centers, log_scales);
    k_reduce<<<128, 256>>>();
    k_small_gemm<<<dim3(64, 4, 2), 256>>>(Wv, 0);
    k_small_gemm<<<dim3(64, 4, 2), 256>>>(Wo, 1);
    k_out<<<512, 256>>>(y);
}

// round 8
// speedup vs baseline: 1.2354x; 1.2354x over previous
#include <cuda_runtime.h>
#include <math.h>

#define Bn 4
#define Tn 8192
#define Dn 512
#define Sn 16
#define PARTS 64   // 256 blocks / 4 batches in the fused attn+G pass

// Scratch (static device globals — allocation-free per harness rules)
__device__ float g_attn [Bn*Tn*Sn];          // 2 MB
__device__ float g_Gpart[Bn*PARTS*Sn*Dn];    // 8 MB
__device__ float g_G    [Bn*Sn*Dn];
__device__ float g_H    [Bn*Sn*Dn];
__device__ float g_M    [Bn*Sn*Dn];

__device__ __forceinline__ unsigned f2tf32(float f) {
    unsigned r; asm("cvt.rna.tf32.f32 %0, %1;" : "=r"(r) : "f"(f));
    return r;
}

__device__ __forceinline__ void mma_tf32(float c[4],
    unsigned a0, unsigned a1, unsigned a2, unsigned a3,
    unsigned b0, unsigned b1) {
    asm("mma.sync.aligned.m16n8k8.row.col.f32.tf32.tf32.f32 "
        "{%0,%1,%2,%3}, {%4,%5,%6,%7}, {%8,%9}, {%0,%1,%2,%3};"
        : "+f"(c[0]), "+f"(c[1]), "+f"(c[2]), "+f"(c[3])
        : "r"(a0), "r"(a1), "r"(a2), "r"(a3), "r"(b0), "r"(b1));
}

// 8-lane reduction (lanes differing in bits 0..2)
__device__ __forceinline__ float red8(float v) {
    v += __shfl_xor_sync(0xffffffffu, v, 1);
    v += __shfl_xor_sync(0xffffffffu, v, 2);
    v += __shfl_xor_sync(0xffffffffu, v, 4);
    return v;
}

// Reduce acc[16] with 16 shuffles; result for index (lane>>1)&15 on even lanes.
__device__ __forceinline__ float reduce16_scatter(float* acc, int lane) {
#pragma unroll
    for (int step = 16, n = 8; n >= 1; step >>= 1, n >>= 1) {
        bool hi = (lane & step) != 0;
#pragma unroll
        for (int i = 0; i < n; i++) {
            float send = hi ? acc[i] : acc[i + n];
            float recv = __shfl_xor_sync(0xffffffffu, send, step);
            acc[i] = (hi ? acc[i + n] : acc[i]) + recv;
        }
    }
    float v = acc[0];
    v += __shfl_xor_sync(0xffffffffu, v, 1);
    return v;
}

// ---------------------------------------------------------------------------
// Kernel 1 (fused): attention weights (tf32 MMA for xc; x2 folded into the
// staging loop, fp32) + partial G = attn^T x (fp32, coalesced).
// Grid 256 x 256 thr, 128 tokens/block.
// ---------------------------------------------------------------------------
__global__ __launch_bounds__(256) void k_attn_g(const float* __restrict__ x,
                                                const float* __restrict__ centers,
                                                const float* __restrict__ log_scales) {
    __shared__ float    s_x   [128 * 36];    // tf32 x chunk, padded (18 KB)
    __shared__ unsigned s_bf  [512];         // B fragments (centers) per chunk (2 KB)
    __shared__ float    s_xc  [128 * 17];    // XC, padded (8.7 KB)
    __shared__ float    s_attn[128 * Sn];    // 8 KB
    __shared__ float    s_x2  [128];
    __shared__ float    s_part[256];
    __shared__ float    s_inv [Sn], s_bias[Sn];

    int tid  = threadIdx.x;
    int warp = tid >> 5, lane = tid & 31;
    int gid  = lane >> 2, tg = lane & 3;     // mma fragment coords
    long long tok0 = (long long)blockIdx.x * 128;
    const float* xb = x + tok0 * Dn;

    // ---- scale/bias precompute: c2 via 16 threads per splat ----
    {
        int sp = tid >> 4, p16 = tid & 15;
        const float4* cr = (const float4*)(centers + (long long)sp * Dn);
        float c2 = 0.f;
#pragma unroll
        for (int j = 0; j < 8; j++) {
            float4 v = cr[p16 + j * 16];
            c2 += v.x * v.x + v.y * v.y + v.z * v.z + v.w * v.w;
        }
        s_part[tid] = c2;
        __syncthreads();
        if (tid < Sn) {
            float c2t = 0.f;
#pragma unroll
            for (int k = 0; k < 16; k++) c2t += s_part[tid * 16 + k];
            float s = expf(log_scales[tid]);
            s = fminf(fmaxf(s, 0.1f), 2.0f);
            float inv = -0.5f / (s * s);
            s_inv[tid]  = inv;
            s_bias[tid] = inv * c2t;
        }
    }

    // ---- Phase 1: XC = x . centers^T via tf32 mma; x2 folded into staging ----
    float xcacc[2][4];
#pragma unroll
    for (int h = 0; h < 2; h++)
#pragma unroll
        for (int r = 0; r < 4; r++) xcacc[h][r] = 0.f;
    float x2p[4] = {0.f, 0.f, 0.f, 0.f};     // partial x2 for rows (tid>>3)+32i, col tid&7
    int tlw = warp * 16;                     // warp's m-tile token base

#pragma unroll 1
    for (int c = 0; c < 16; c++) {
        // stage x chunk (cols c*32..+31) as tf32, padded stride 36; fold x2
#pragma unroll
        for (int i = 0; i < 4; i++) {
            int row = (tid >> 3) + i * 32, c4 = tid & 7;
            float4 v = ((const float4*)(xb + (long long)row * Dn))[c * 8 + c4];
            x2p[i] += v.x * v.x + v.y * v.y + v.z * v.z + v.w * v.w;
            float4 t;
            t.x = __uint_as_float(f2tf32(v.x));
            t.y = __uint_as_float(f2tf32(v.y));
            t.z = __uint_as_float(f2tf32(v.z));
            t.w = __uint_as_float(f2tf32(v.w));
            *(float4*)&s_x[row * 36 + c4 * 4] = t;
        }
        // B fragments for this chunk: [kit8][h][which][lane]
#pragma unroll
        for (int i = 0; i < 2; i++) {
            int e = tid + i * 256;           // 0..511
            int kit8 = e >> 7, rem = e & 127;
            int h = rem >> 6, which = (rem >> 5) & 1, L = rem & 31;
            int k  = c * 32 + kit8 * 8 + (L & 3) + which * 4;
            int sp = h * 8 + (L >> 2);
            s_bf[e] = f2tf32(centers[(long long)sp * Dn + k]);
        }
        __syncthreads();
        // 4 k-iterations of m16n8k8 per n-half
#pragma unroll
        for (int kit8 = 0; kit8 < 4; kit8++) {
            int kb = kit8 * 8;
            unsigned a0 = __float_as_uint(s_x[(tlw + gid)     * 36 + kb + tg]);
            unsigned a1 = __float_as_uint(s_x[(tlw + gid + 8) * 36 + kb + tg]);
            unsigned a2 = __float_as_uint(s_x[(tlw + gid)     * 36 + kb + tg + 4]);
            unsigned a3 = __float_as_uint(s_x[(tlw + gid + 8) * 36 + kb + tg + 4]);
#pragma unroll
            for (int h = 0; h < 2; h++) {
                unsigned b0 = s_bf[kit8 * 128 + h * 64 + lane];
                unsigned b1 = s_bf[kit8 * 128 + h * 64 + 32 + lane];
                mma_tf32(xcacc[h], a0, a1, a2, a3, b0, b1);
            }
        }
        __syncthreads();
    }

    // write XC fragments to padded smem
#pragma unroll
    for (int h = 0; h < 2; h++) {
        int col = h * 8 + tg * 2;
        s_xc[(tlw + gid)     * 17 + col]     = xcacc[h][0];
        s_xc[(tlw + gid)     * 17 + col + 1] = xcacc[h][1];
        s_xc[(tlw + gid + 8) * 17 + col]     = xcacc[h][2];
        s_xc[(tlw + gid + 8) * 17 + col + 1] = xcacc[h][3];
    }
    // finish x2: threads sharing a row differ in lane bits 0..2
#pragma unroll
    for (int i = 0; i < 4; i++) {
        float v = red8(x2p[i]);
        if ((tid & 7) == 0) s_x2[(tid >> 3) + i * 32] = v;
    }
    __syncthreads();

    // per-token softmax (threads 0..127)
    if (tid < 128) {
        float x2 = s_x2[tid];
        float l[Sn];
        float m = -1e30f;
#pragma unroll
        for (int s = 0; s < Sn; s++) {
            l[s] = s_inv[s] * (x2 - 2.f * s_xc[tid * 17 + s]) + s_bias[s];
            m = fmaxf(m, l[s]);
        }
        float sum = 0.f;
#pragma unroll
        for (int s = 0; s < Sn; s++) { l[s] = __expf(l[s] - m); sum += l[s]; }
        float r = 1.f / sum;
#pragma unroll
        for (int s = 0; s < Sn; s++) s_attn[tid * Sn + s] = l[s] * r;
    }
    __syncthreads();

    // coalesced copy s_attn -> g_attn
    for (int i = tid; i < 128 * Sn / 4; i += 256)
        ((float4*)(g_attn + tok0 * Sn))[i] = ((const float4*)s_attn)[i];

    // -------- Phase 2: G partial over this block's 128 tokens (fp32) --------
    float2 accG[Sn];
#pragma unroll
    for (int s = 0; s < Sn; s++) { accG[s].x = 0.f; accG[s].y = 0.f; }

#pragma unroll 4
    for (int t = 0; t < 128; t++) {
        float2 xv = ((const float2*)(xb + (long long)t * Dn))[tid];   // d = 2*tid, 2*tid+1
        const float4* ar = (const float4*)&s_attn[t * Sn];
#pragma unroll
        for (int q = 0; q < 4; q++) {
            float4 a = ar[q];
            accG[q*4+0].x += a.x * xv.x; accG[q*4+0].y += a.x * xv.y;
            accG[q*4+1].x += a.y * xv.x; accG[q*4+1].y += a.y * xv.y;
            accG[q*4+2].x += a.z * xv.x; accG[q*4+2].y += a.z * xv.y;
            accG[q*4+3].x += a.w * xv.x; accG[q*4+3].y += a.w * xv.y;
        }
    }

    int b = (int)(tok0 / Tn);
    int p = (int)((tok0 % Tn) / 128);
    float* gp = g_Gpart + ((long long)(b * PARTS + p) * Sn * Dn);
#pragma unroll
    for (int s = 0; s < Sn; s++)
        ((float2*)(gp + s * Dn))[tid] = accG[s];
}

// ---------------------------------------------------------------------------
// Kernel 2: reduce 64 partials -> G. 32768 outputs. Grid 128 x 256 thr.
// ---------------------------------------------------------------------------
__global__ void k_reduce() {
    int idx = blockIdx.x * blockDim.x + threadIdx.x;   // < Bn*Sn*Dn = 32768
    int b = idx >> 13;
    int r = idx & 8191;
    float sum = 0.f;
#pragma unroll
    for (int p = 0; p < PARTS; p++)
        sum += g_Gpart[(long long)(b * PARTS + p) * (Sn * Dn) + r];
    g_G[idx] = sum;
}

// ---------------------------------------------------------------------------
// Kernel 3: small GEMM out[row][k] = sum_d in[row][d] * W[k][d], rows = 64.
// Round-6 measured-best (7.17us): 16 in-rows in smem, warp-per-column,
// plain float4 FMA, reduce-scatter finish.
// ---------------------------------------------------------------------------
__global__ __launch_bounds__(256) void k_small_gemm(const float* __restrict__ W, int stage) {
    const float* in  = (stage == 0) ? g_G : g_H;
    float*       out = (stage == 0) ? g_H : g_M;
    __shared__ float4 s_in[16 * 128];        // 32 KB

    int tid = threadIdx.x, warp = tid >> 5, lane = tid & 31;
    int kc = blockIdx.x;                     // 0..63 column chunk
    int b  = blockIdx.y;                     // 0..3 batch

    const float4* src = (const float4*)(in + (long long)b * 16 * Dn);
#pragma unroll
    for (int i = 0; i < 8; i++) s_in[tid + i * 256] = src[tid + i * 256];
    __syncthreads();

    int k = kc * 8 + warp;                   // output column, 0..511
    const float4* wr = (const float4*)(W + (long long)k * Dn);
    float4 w0 = wr[lane], w1 = wr[lane + 32], w2 = wr[lane + 64], w3 = wr[lane + 96];

    float acc[16];
#pragma unroll
    for (int r = 0; r < 16; r++) {
        float4 g0 = s_in[r * 128 + lane];
        float4 g1 = s_in[r * 128 + lane + 32];
        float4 g2 = s_in[r * 128 + lane + 64];
        float4 g3 = s_in[r * 128 + lane + 96];
        acc[r] = w0.x*g0.x + w0.y*g0.y + w0.z*g0.z + w0.w*g0.w
               + w1.x*g1.x + w1.y*g1.y + w1.z*g1.z + w1.w*g1.w
               + w2.x*g2.x + w2.y*g2.y + w2.z*g2.z + w2.w*g2.w
               + w3.x*g3.x + w3.y*g3.y + w3.z*g3.z + w3.w*g3.w;
    }
    float val = reduce16_scatter(acc, lane);
    int row = (lane >> 1) & 15;
    if ((lane & 1) == 0)
        out[(long long)(b * 16 + row) * Dn + k] = val;
}

// ---------------------------------------------------------------------------
// Kernel 4: y[t,:] = sum_s attn[t,s] * M[b,s,:]. Grid 256 x 256 thr,
// 128 tokens/block; thread owns 4 dims (float4), half=tid>>7 picks 64 tokens;
// M columns in 16 float4 registers; STG.128 stores.
// ---------------------------------------------------------------------------
__global__ __launch_bounds__(256) void k_out(float* __restrict__ y) {
    __shared__ float s_a[128 * Sn];          // 8 KB attn tile
    int tid = threadIdx.x;
    long long tok0 = (long long)blockIdx.x * 128;
    int b = (int)(tok0 / Tn);

#pragma unroll
    for (int i = 0; i < 2; i++)
        ((float4*)s_a)[tid + i * 256] = ((const float4*)(g_attn + tok0 * Sn))[tid + i * 256];
    __syncthreads();

    int dg = tid & 127, half = tid >> 7;
    const float* Mb = g_M + (long long)b * Sn * Dn;
    float4 m[Sn];
#pragma unroll
    for (int s = 0; s < Sn; s++) m[s] = ((const float4*)(Mb + s * Dn))[dg];

    float* yb = y + (tok0 + half * 64) * Dn;
#pragma unroll 2
    for (int t = 0; t < 64; t++) {
        const float4* ar = (const float4*)&s_a[(half * 64 + t) * Sn];
        float4 o; o.x = 0.f; o.y = 0.f; o.z = 0.f; o.w = 0.f;
#pragma unroll
        for (int q = 0; q < 4; q++) {
            float4 a = ar[q];
#pragma unroll
            for (int j = 0; j < 4; j++) {
                float av = (j == 0) ? a.x : (j == 1) ? a.y : (j == 2) ? a.z : a.w;
                float4 mv = m[q * 4 + j];
                o.x += av * mv.x; o.y += av * mv.y;
                o.z += av * mv.z; o.w += av * mv.w;
            }
        }
        ((float4*)(yb + (long long)t * Dn))[dg] = o;
    }
}

// ---------------------------------------------------------------------------
extern "C" void kernel_launch(void* const* d_in, const int* in_sizes, int n_in,
                              void* d_out, int out_size) {
    (void)in_sizes; (void)n_in; (void)out_size;
    const float* x          = (const float*)d_in[0];   // [B,T,D]
    const float* centers    = (const float*)d_in[1];   // [S,D]
    const float* log_scales = (const float*)d_in[2];   // [S]
    const float* Wv         = (const float*)d_in[3];   // [D,D]
    const float* Wo         = (const float*)d_in[4];   // [D,D]
    float* y = (float*)d_out;                          // [B,T,D] fp32

    k_attn_g<<<256, 256>>>(x, centers, log_scales);
    k_reduce<<<128, 256>>>();
    k_small_gemm<<<dim3(64, 4), 256>>>(Wv, 0);
    k_small_gemm<<<dim3(64, 4), 256>>>(Wo, 1);
    k_out<<<256, 256>>>(y);
}